// round 1
// baseline (speedup 1.0000x reference)
#include <cuda_runtime.h>
#include <float.h>

// Problem constants
#define B_  16
#define P_  4096
#define T_  1024
#define G_  64                 // 64x64 cells of size 8.0 covering [0,512)
#define NC_ (G_*G_)
#define CAP_ 16                // slots per cell; overflow list handles the (near-impossible) rest
#define RADIUS_ 2.5f
#define SENT_ 0xFFFFFFFFFFFFFFFFull

// Scratch (device globals: no allocation allowed)
__device__ int                g_cnt [B_*NC_];
__device__ float4             g_cell[B_*NC_*CAP_];
__device__ int                g_ovfn[B_];
__device__ float4             g_ovf [B_*T_];
__device__ unsigned long long g_best[B_*T_];     // packed (dsq_bits<<32)|p ; min => min d then min p
__device__ float              g_mind[B_*P_];     // per-pred min dsq over candidate set
__device__ int                g_corr[B_*P_];

__global__ void k_init() {
    int i = blockIdx.x * blockDim.x + threadIdx.x;   // 65536 threads
    g_cnt[i]  = 0;            // B_*NC_ == 65536
    g_corr[i] = 0;            // B_*P_  == 65536
    if (i < B_*T_) g_best[i] = SENT_;
    if (i < B_)    g_ovfn[i] = 0;
}

__global__ void k_bin(const float* __restrict__ gt) {
    int i = blockIdx.x * blockDim.x + threadIdx.x;   // B_*T_ threads
    if (i >= B_*T_) return;
    int b = i >> 10;
    int t = i & (T_ - 1);
    const float* g = gt + (size_t)i * 3;
    float tc = g[0], tx = g[1], ty = g[2];
    int cx = (int)(tx * 0.125f); cx = min(max(cx, 0), G_-1);
    int cy = (int)(ty * 0.125f); cy = min(max(cy, 0), G_-1);
    int c = b*NC_ + cy*G_ + cx;
    int pos = atomicAdd(&g_cnt[c], 1);
    float4 v = make_float4(tc, tx, ty, __int_as_float(t));
    if (pos < CAP_) {
        g_cell[c*CAP_ + pos] = v;
    } else {
        int j = atomicAdd(&g_ovfn[b], 1);
        g_ovf[b*T_ + j] = v;
    }
}

__device__ __forceinline__ void consider(float4 v, float cls, float x, float y,
                                         int p, unsigned long long* bestBase,
                                         float& mind) {
    float dx = x - v.y, dy = y - v.z;
    float dsq = dx*dx + dy*dy;
    mind = fminf(mind, dsq);
    float d = sqrtf(dsq + 1e-12f);
    if (d <= RADIUS_ && cls == v.x) {
        int t = __float_as_int(v.w);
        unsigned long long key = ((unsigned long long)__float_as_uint(dsq) << 32)
                               | (unsigned int)p;
        atomicMin(bestBase + t, key);
    }
}

__global__ void k_pair(const float* __restrict__ pred) {
    int i = blockIdx.x * blockDim.x + threadIdx.x;   // B_*P_ threads
    if (i >= B_*P_) return;
    int b = i >> 12;
    int p = i & (P_ - 1);
    float4 pr = reinterpret_cast<const float4*>(pred)[i];   // {cls, x, y, conf}
    float cls = pr.x, x = pr.y, y = pr.z;

    int cx = (int)(x * 0.125f); cx = min(max(cx, 0), G_-1);
    int cy = (int)(y * 0.125f); cy = min(max(cy, 0), G_-1);
    int x0 = max(cx-1, 0), x1 = min(cx+1, G_-1);
    int y0 = max(cy-1, 0), y1 = min(cy+1, G_-1);

    unsigned long long* bestBase = g_best + b*T_;
    float mind = FLT_MAX;

    for (int yy = y0; yy <= y1; yy++) {
        for (int xx = x0; xx <= x1; xx++) {
            int c = b*NC_ + yy*G_ + xx;
            int cnt = min(g_cnt[c], CAP_);
            const float4* slot = &g_cell[c*CAP_];
            for (int j = 0; j < cnt; j++)
                consider(slot[j], cls, x, y, p, bestBase, mind);
        }
    }
    // Overflow (normally empty): guarantees every target within d<=2.5 is seen
    int novf = g_ovfn[b];
    for (int j = 0; j < novf; j++)
        consider(g_ovf[b*T_ + j], cls, x, y, p, bestBase, mind);

    g_mind[i] = mind;
}

__global__ void k_tgt() {
    int i = blockIdx.x * blockDim.x + threadIdx.x;   // B_*T_ threads
    if (i >= B_*T_) return;
    unsigned long long v = g_best[i];
    if (v != SENT_) {
        int b = i >> 10;
        int p = (int)(v & 0xFFFFFFFFull);
        g_corr[b*P_ + p] = 1;                        // benign race: all write 1
    }
}

__global__ void k_final(const float* __restrict__ pred, float* __restrict__ out) {
    __shared__ double s_obj[1024];
    __shared__ double s_reg[1024];
    int tid = threadIdx.x;
    double so = 0.0, sr = 0.0;
    #pragma unroll 4
    for (int k = 0; k < 64; k++) {
        int i = tid + k * 1024;                      // fixed order -> deterministic
        float conf = pred[4*i + 3];
        int   c    = g_corr[i];
        float cf   = (float)c;
        float bce  = fmaxf(conf, 0.0f) - conf*cf + log1pf(expf(-fabsf(conf)));
        so += (double)bce;
        float rt = 1.0f;
        if (c) {
            float d = sqrtf(g_mind[i] + 1e-12f);     // d <= 2.5 for correct preds
            float s = 1.0f / (1.0f + expf(-(RADIUS_ - d)));
            rt = 1.0f - s;
        }
        sr += (double)rt;
    }
    s_obj[tid] = so; s_reg[tid] = sr;
    __syncthreads();
    for (int off = 512; off > 0; off >>= 1) {
        if (tid < off) { s_obj[tid] += s_obj[tid+off]; s_reg[tid] += s_reg[tid+off]; }
        __syncthreads();
    }
    if (tid == 0) {
        out[0] = (float)(s_obj[0] / 65536.0);  // obj_loss
        out[1] = (float)(s_reg[0] / 65536.0);  // reg_loss
    }
}

extern "C" void kernel_launch(void* const* d_in, const int* in_sizes, int n_in,
                              void* d_out, int out_size) {
    const float* pred = (const float*)d_in[0];
    const float* gt   = (const float*)d_in[1];
    // Defensive: identify by element count (pred = 16*4096*4, gt = 16*1024*3)
    if (n_in >= 2 && in_sizes[0] == B_*T_*3) {
        const float* tmp = pred; pred = gt; gt = tmp;
    }
    float* out = (float*)d_out;
    (void)out_size;

    k_init <<<256, 256>>>();
    k_bin  <<<64, 256>>>(gt);
    k_pair <<<256, 256>>>(pred);
    k_tgt  <<<64, 256>>>();
    k_final<<<1, 1024>>>(pred, out);
}

// round 2
// speedup vs baseline: 2.7369x; 2.7369x over previous
#include <cuda_runtime.h>
#include <float.h>

// Problem constants
#define B_   16
#define P_   4096
#define T_   1024
#define G_   64                 // 64x64 cells of size 8.0 covering [0,512)
#define NC_  (G_*G_)
#define CAP_ 16
#define RADIUS_ 2.5f
#define SENT_ 0xFFFFFFFFFFFFFFFFull

#define NB_   148               // <= SM count -> all blocks co-resident -> grid barrier safe
#define NT_   256
#define NTOT_ (NB_*NT_)

// Scratch (device globals: no allocation allowed)
__device__ int                g_cnt [B_*NC_];
__device__ float4             g_cell[B_*NC_*CAP_];
__device__ int                g_ovfn[B_];
__device__ float4             g_ovf [B_*T_];
__device__ unsigned long long g_best[B_*T_];     // packed (dsq_bits<<32)|p ; min => min d then min p
__device__ float              g_mind[B_*P_];
__device__ int                g_corr[B_*P_];
__device__ double             g_pobj[NB_];
__device__ double             g_preg[NB_];
__device__ volatile unsigned long long g_bar;    // monotonic ticket barrier (never reset)

// Grid-wide barrier: monotonic counter, works across uses and across graph replays.
__device__ __forceinline__ void gbar() {
    __syncthreads();
    if (threadIdx.x == 0) {
        __threadfence();  // make this block's writes L2-visible before arrival
        unsigned long long my = atomicAdd((unsigned long long*)&g_bar, 1ull);
        unsigned long long tgt = (my / NB_ + 1ull) * NB_;
        while (g_bar < tgt) __nanosleep(32);
    }
    __syncthreads();
}

__device__ __forceinline__ void consider(float4 v, float cls, float x, float y,
                                         int p, unsigned long long* bestBase,
                                         float& mind) {
    float dx = x - v.y, dy = y - v.z;
    float dsq = dx*dx + dy*dy;
    mind = fminf(mind, dsq);
    float d = sqrtf(dsq + 1e-12f);
    if (d <= RADIUS_ && cls == v.x) {
        int t = __float_as_int(v.w);
        unsigned long long key = ((unsigned long long)__float_as_uint(dsq) << 32)
                               | (unsigned int)p;
        atomicMin(bestBase + t, key);
    }
}

__global__ void __launch_bounds__(NT_, 1)
fused_kernel(const float* __restrict__ pred, const float* __restrict__ gt,
             float* __restrict__ out) {
    const int tid = threadIdx.x;
    const int gt0 = blockIdx.x * NT_ + tid;

    // ---- Phase 0: init scratch -------------------------------------------
    for (int i = gt0; i < B_*NC_; i += NTOT_) g_cnt[i] = 0;     // 65536
    for (int i = gt0; i < B_*P_;  i += NTOT_) g_corr[i] = 0;    // 65536
    for (int i = gt0; i < B_*T_;  i += NTOT_) g_best[i] = SENT_;
    if (gt0 < B_) g_ovfn[gt0] = 0;
    gbar();

    // ---- Phase 1: bin targets into spatial hash --------------------------
    for (int i = gt0; i < B_*T_; i += NTOT_) {
        int b = i >> 10;
        int t = i & (T_ - 1);
        const float* g = gt + (size_t)i * 3;
        float tc = g[0], tx = g[1], ty = g[2];
        int cx = (int)(tx * 0.125f); cx = min(max(cx, 0), G_-1);
        int cy = (int)(ty * 0.125f); cy = min(max(cy, 0), G_-1);
        int c = b*NC_ + cy*G_ + cx;
        int pos = atomicAdd(&g_cnt[c], 1);
        float4 v = make_float4(tc, tx, ty, __int_as_float(t));
        if (pos < CAP_) {
            g_cell[c*CAP_ + pos] = v;
        } else {
            int j = atomicAdd(&g_ovfn[b], 1);
            g_ovf[b*T_ + j] = v;
        }
    }
    gbar();

    // ---- Phase 2: per-pred 3x3 neighborhood scan -------------------------
    for (int i = gt0; i < B_*P_; i += NTOT_) {
        int b = i >> 12;
        int p = i & (P_ - 1);
        float4 pr = __ldg(reinterpret_cast<const float4*>(pred) + i);  // {cls,x,y,conf}
        float cls = pr.x, x = pr.y, y = pr.z;

        int cx = (int)(x * 0.125f); cx = min(max(cx, 0), G_-1);
        int cy = (int)(y * 0.125f); cy = min(max(cy, 0), G_-1);
        int x0 = max(cx-1, 0), x1 = min(cx+1, G_-1);
        int y0 = max(cy-1, 0), y1 = min(cy+1, G_-1);

        unsigned long long* bestBase = g_best + b*T_;
        float mind = FLT_MAX;

        for (int yy = y0; yy <= y1; yy++) {
            for (int xx = x0; xx <= x1; xx++) {
                int c = b*NC_ + yy*G_ + xx;
                int cnt = min(__ldcg(&g_cnt[c]), CAP_);
                const float4* slot = &g_cell[c*CAP_];
                for (int j = 0; j < cnt; j++)
                    consider(__ldcg(slot + j), cls, x, y, p, bestBase, mind);
            }
        }
        int novf = __ldcg(&g_ovfn[b]);     // normally 0
        for (int j = 0; j < novf; j++)
            consider(__ldcg(&g_ovf[b*T_ + j]), cls, x, y, p, bestBase, mind);

        g_mind[i] = mind;
    }
    gbar();

    // ---- Phase 3: scatter correctness flags ------------------------------
    for (int i = gt0; i < B_*T_; i += NTOT_) {
        unsigned long long v = __ldcg(&g_best[i]);
        if (v != SENT_) {
            int b = i >> 10;
            int p = (int)(v & 0xFFFFFFFFull);
            g_corr[b*P_ + p] = 1;          // benign race: all write 1
        }
    }
    gbar();

    // ---- Phase 4: parallel deterministic reduction -----------------------
    __shared__ double s_obj[NT_];
    __shared__ double s_reg[NT_];
    double so = 0.0, sr = 0.0;
    for (int i = gt0; i < B_*P_; i += NTOT_) {   // fixed per-thread order
        float conf = __ldg(&pred[4*i + 3]);
        int   c    = __ldcg(&g_corr[i]);
        float cf   = (float)c;
        float bce  = fmaxf(conf, 0.0f) - conf*cf + log1pf(expf(-fabsf(conf)));
        so += (double)bce;
        float rt = 1.0f;
        if (c) {
            float d = sqrtf(__ldcg(&g_mind[i]) + 1e-12f);
            float s = 1.0f / (1.0f + expf(-(RADIUS_ - d)));
            rt = 1.0f - s;
        }
        sr += (double)rt;
    }
    s_obj[tid] = so; s_reg[tid] = sr;
    __syncthreads();
    for (int off = NT_/2; off > 0; off >>= 1) {
        if (tid < off) { s_obj[tid] += s_obj[tid+off]; s_reg[tid] += s_reg[tid+off]; }
        __syncthreads();
    }
    if (tid == 0) { g_pobj[blockIdx.x] = s_obj[0]; g_preg[blockIdx.x] = s_reg[0]; }
    gbar();

    // ---- Phase 5: block 0 combines 148 partials (fixed tree) -------------
    if (blockIdx.x == 0) {
        double a = 0.0, r = 0.0;
        if (tid < NB_) { a = __ldcg(&g_pobj[tid]); r = __ldcg(&g_preg[tid]); }
        s_obj[tid] = a; s_reg[tid] = r;
        __syncthreads();
        for (int off = NT_/2; off > 0; off >>= 1) {
            if (tid < off) { s_obj[tid] += s_obj[tid+off]; s_reg[tid] += s_reg[tid+off]; }
            __syncthreads();
        }
        if (tid == 0) {
            out[0] = (float)(s_obj[0] / 65536.0);   // obj_loss
            out[1] = (float)(s_reg[0] / 65536.0);   // reg_loss
        }
    }
}

extern "C" void kernel_launch(void* const* d_in, const int* in_sizes, int n_in,
                              void* d_out, int out_size) {
    const float* pred = (const float*)d_in[0];
    const float* gt   = (const float*)d_in[1];
    if (n_in >= 2 && in_sizes[0] == B_*T_*3) {   // defensive input-order check
        const float* tmp = pred; pred = gt; gt = tmp;
    }
    (void)out_size;
    fused_kernel<<<NB_, NT_>>>(pred, gt, (float*)d_out);
}